// round 14
// baseline (speedup 1.0000x reference)
#include <cuda_runtime.h>

#define E_EDGE 8192
#define BATCH  32
#define N_VAR  2048

// scratch: input transposed to [k][b] (1 MB) and llr pre-scaled+transposed to [v][b] (256 KB)
__device__ float g_inputT[E_EDGE * BATCH];
__device__ float g_llrT[N_VAR * BATCH];

__global__ __launch_bounds__(256) void prep_kernel(const float* __restrict__ input,
                                                   const float* __restrict__ llr,
                                                   const float* __restrict__ llr_w) {
    int tid = blockIdx.x * blockDim.x + threadIdx.x;
    if (tid < E_EDGE * BATCH) {
        int b = tid >> 13;           // tid / 8192  (coalesced read along k)
        int k = tid & (E_EDGE - 1);
        g_inputT[k * BATCH + b] = input[tid];
    } else {
        int t = tid - E_EDGE * BATCH;
        if (t < N_VAR * BATCH) {
            int b = t >> 11;         // t / 2048
            int v = t & (N_VAR - 1);
            g_llrT[v * BATCH + b] = llr[t] * llr_w[v];
        }
    }
}

// One warp per output row e_out; lane = batch b.
// Weight is never streamed (mask*weight == 0 wherever mask == 0 for ANY weight
// values); it's gathered as one float4 per hit (~8 hits per row of 8192).
// R14 KEY: the only configuration that ever exceeded the ~60-66% DRAM plateau
// was R3's 32-reg / near-full-occupancy binary (82.6% occ -> 74.5% DRAM).
// Under loaded-DRAM latency, resident-warp count is the dominant outstanding-
// request multiplier. So: force the 32-reg budget (LB 256,8 -> 64 warps/SM
// theoretical) and keep the loop minimal to avoid spills.
__global__ __launch_bounds__(256, 8) void bp_main_kernel(
    const float* __restrict__ mask,
    const float* __restrict__ weight,
    float* __restrict__ out)
{
    const int warp = threadIdx.x >> 5;          // 0..7
    const int lane = threadIdx.x & 31;          // batch b
    const int row0 = blockIdx.x << 3;           // 8 rows per block
    const int row  = row0 + warp;               // e_out

    const float4* __restrict__ m4 = reinterpret_cast<const float4*>(mask + (size_t)row * E_EDGE);

    float acc = 0.0f;

    // 16 groups × (4 chunks × 32 lanes × 4 floats) = 8192
    for (int g = 0; g < E_EDGE / 512; ++g) {
        float4 m[4];
        #pragma unroll
        for (int it = 0; it < 4; ++it)
            m[it] = __ldcs(&m4[(g * 4 + it) * 32 + lane]);

        #pragma unroll
        for (int it = 0; it < 4; ++it) {
            // integer nz test; <<1 drops sign bit so ±0.0 is skipped (exact)
            unsigned bits = (__float_as_uint(m[it].x) | __float_as_uint(m[it].y) |
                             __float_as_uint(m[it].z) | __float_as_uint(m[it].w)) << 1;
            unsigned ball = __ballot_sync(0xFFFFFFFFu, bits != 0u);

            // rare path: ~8 nonzeros per whole row of 8192
            while (ball) {
                int src = __ffs(ball) - 1;
                ball &= ball - 1;
                float mx = __shfl_sync(0xFFFFFFFFu, m[it].x, src);
                float my = __shfl_sync(0xFFFFFFFFu, m[it].y, src);
                float mz = __shfl_sync(0xFFFFFFFFu, m[it].z, src);
                float mw = __shfl_sync(0xFFFFFFFFu, m[it].w, src);
                const int k0 = (g * 4 + it) * 128 + src * 4;
                // one 16B broadcast gather of the weight (rare-path only)
                const float4 w4 = __ldg(reinterpret_cast<const float4*>(
                                            weight + (size_t)row * E_EDGE + k0));
                const float* t = g_inputT + (size_t)k0 * BATCH + lane;  // coalesced
                if (mx != 0.0f) acc = fmaf(mx * w4.x, t[0 * BATCH], acc);
                if (my != 0.0f) acc = fmaf(my * w4.y, t[1 * BATCH], acc);
                if (mz != 0.0f) acc = fmaf(mz * w4.z, t[2 * BATCH], acc);
                if (mw != 0.0f) acc = fmaf(mw * w4.w, t[3 * BATCH], acc);
            }
        }
    }

    // epilogue: llr term (pre-scaled, coalesced) + smem transpose for full-sector stores
    __shared__ float tile[8][33];
    tile[warp][lane] = 0.5f * (g_llrT[(row & (N_VAR - 1)) * BATCH + lane] + acc);
    __syncthreads();

    // thread t: b = t>>3 (0..31), el = t&7 -> each 8-thread group writes one
    // full, aligned 32B sector of out[b][row0 .. row0+7]
    const int b  = threadIdx.x >> 3;
    const int el = threadIdx.x & 7;
    out[(size_t)b * E_EDGE + row0 + el] = tile[el][b];
}

extern "C" void kernel_launch(void* const* d_in, const int* in_sizes, int n_in,
                              void* d_out, int out_size) {
    const float* input    = (const float*)d_in[0];  // [32, 8192]
    const float* input_w  = (const float*)d_in[1];  // [8192, 8192]
    const float* mask     = (const float*)d_in[2];  // [8192, 8192]
    const float* llr      = (const float*)d_in[3];  // [32, 2048]
    const float* llr_w    = (const float*)d_in[4];  // [1, 2048]
    // d_in[5] = llr_expander (one-hot of e % N_VAR) — realized via index math
    float* out = (float*)d_out;                     // [32, 8192]

    (void)in_sizes; (void)n_in; (void)out_size;

    const int prep_n = E_EDGE * BATCH + N_VAR * BATCH;
    prep_kernel<<<(prep_n + 255) / 256, 256>>>(input, llr, llr_w);

    // 8192 rows, 8 rows (warps) per 256-thread block
    bp_main_kernel<<<E_EDGE / 8, 256>>>(mask, input_w, out);
}